// round 2
// baseline (speedup 1.0000x reference)
#include <cuda_runtime.h>

typedef unsigned long long u64;

#define RW 192
#define TW 182
#define TH 16
#define RH 26          // TH + 10
#define HALF 96        // column-pair distance; thread t owns cols t and t+96
#define WSTRIDE 97     // odd -> conflict-free 64-bit smem accesses
#define NTHREADS 96
#define IMG_W 512
#define IMG_H 512
#define PLANES 96
#define NBLOCKS (3 * 32 * 96)
#define NPIX 25165824.0f

static constexpr float W0 = 0.00102838f;
static constexpr float W1 = 0.00759876f;
static constexpr float W2 = 0.03600077f;
static constexpr float W3 = 0.10936069f;
static constexpr float W4 = 0.21300553f;
static constexpr float W5 = 0.26601172f;
static constexpr float C1V = 0.0001f;
static constexpr float C2V = 0.0009f;

__device__ float g_accum;
__device__ unsigned int g_count;

// ---- packed f32x2 helpers (sm_100+) ----
__device__ __forceinline__ u64 pack2(float lo, float hi) {
    u64 r; asm("mov.b64 %0, {%1, %2};" : "=l"(r) : "f"(lo), "f"(hi)); return r;
}
__device__ __forceinline__ void unpack2(u64 v, float& lo, float& hi) {
    asm("mov.b64 {%0, %1}, %2;" : "=f"(lo), "=f"(hi) : "l"(v));
}
__device__ __forceinline__ u64 fma2(u64 a, u64 b, u64 c) {
    u64 d; asm("fma.rn.f32x2 %0, %1, %2, %3;" : "=l"(d) : "l"(a), "l"(b), "l"(c)); return d;
}
__device__ __forceinline__ u64 mul2(u64 a, u64 b) {
    u64 d; asm("mul.rn.f32x2 %0, %1, %2;" : "=l"(d) : "l"(a), "l"(b)); return d;
}
__device__ __forceinline__ u64 add2(u64 a, u64 b) {
    u64 d; asm("add.rn.f32x2 %0, %1, %2;" : "=l"(d) : "l"(a), "l"(b)); return d;
}
__device__ __forceinline__ u64 sub2(u64 a, u64 b) {
    u64 d; asm("sub.rn.f32x2 %0, %1, %2;" : "=l"(d) : "l"(a), "l"(b)); return d;
}

__device__ __forceinline__ int widx(int k) { return (k < 6) ? k : (10 - k); }

__global__ void __launch_bounds__(NTHREADS)
ssim_main(const float* __restrict__ img1, const float* __restrict__ img2,
          float* __restrict__ out) {
    extern __shared__ u64 v[];           // [5][TH][WSTRIDE] packed column pairs
    __shared__ float red[NTHREADS / 32]; // warp partials

    const int tx = threadIdx.x;
    const int plane = blockIdx.z;
    const int x0 = blockIdx.x * TW;
    const int y0 = blockIdx.y * TH;

    const float* __restrict__ p1 = img1 + (size_t)plane * (IMG_W * IMG_H);
    const float* __restrict__ p2 = img2 + (size_t)plane * (IMG_W * IMG_H);

    const int gxl = x0 - 5 + tx;      // low column of the pair
    const int gxh = gxl + HALF;       // high column (always >= 91)
    const bool okl = (gxl >= 0) && (gxl < IMG_W);
    const bool okh = (gxh < IMG_W);

    // packed weights / constants
    const float ws[6] = {W0, W1, W2, W3, W4, W5};
    u64 Wp[6];
#pragma unroll
    for (int i = 0; i < 6; i++) Wp[i] = pack2(ws[i], ws[i]);
    const u64 C1p = pack2(C1V, C1V);
    const u64 C2p = pack2(C2V, C2V);

    u64 acc[5][11];
#pragma unroll
    for (int q = 0; q < 5; q++)
#pragma unroll
        for (int j = 0; j < 11; j++) acc[q][j] = 0ULL;

    // ---------- Phase B: vertical blur (global -> packed smem), transposed accumulation ----------
#pragma unroll
    for (int r = 0; r < RH; r++) {
        const int gy = y0 - 5 + r;
        const bool yok = (gy >= 0) && (gy < IMG_H);
        float a0 = 0.f, b0 = 0.f, a1 = 0.f, b1 = 0.f;
        if (yok) {
            const int base = gy * IMG_W;
            if (okl) { a0 = __ldg(p1 + base + gxl); b0 = __ldg(p2 + base + gxl); }
            if (okh) { a1 = __ldg(p1 + base + gxh); b1 = __ldg(p2 + base + gxh); }
        }
        const u64 A  = pack2(a0, a1);
        const u64 B  = pack2(b0, b1);
        u64 pq[5];
        pq[0] = A; pq[1] = B;
        pq[2] = mul2(A, A); pq[3] = mul2(B, B); pq[4] = mul2(A, B);
#pragma unroll
        for (int k = 0; k < 11; k++) {
            const int o = r - k;
            if (o >= 0 && o < TH) {
                const int j = o % 11;
#pragma unroll
                for (int q = 0; q < 5; q++)
                    acc[q][j] = fma2(pq[q], Wp[widx(k)], acc[q][j]);
            }
        }
        if (r >= 10) {
            const int o = r - 10;
            const int j = o % 11;
#pragma unroll
            for (int q = 0; q < 5; q++) {
                v[(q * TH + o) * WSTRIDE + tx] = acc[q][j];
                acc[q][j] = 0ULL;
            }
        }
    }
    __syncthreads();

    // ---------- Phase C: horizontal blur + SSIM epilogue ----------
    const int row = tx & 15;      // 0..15
    const int seg = tx >> 4;      // 0..5 ; thread covers output segs seg and seg+6
    const int cbase = seg * 16;

#pragma unroll
    for (int q = 0; q < 5; q++)
#pragma unroll
        for (int j = 0; j < 11; j++) acc[q][j] = 0ULL;

    float lsum = 0.f;
#pragma unroll
    for (int i = 0; i < RH; i++) {
        const int w = cbase + i;          // 0..105
        u64 pv[5];
        if (w < HALF) {
#pragma unroll
            for (int q = 0; q < 5; q++)
                pv[q] = v[(q * TH + row) * WSTRIDE + w];
        } else {
            // col w lives in the HIGH half of word (w-96); col w+96 is out of tile
            const float* vf = (const float*)v;
#pragma unroll
            for (int q = 0; q < 5; q++) {
                const float lo = vf[2 * ((q * TH + row) * WSTRIDE + (w - HALF)) + 1];
                pv[q] = pack2(lo, 0.f);
            }
        }
#pragma unroll
        for (int k = 0; k < 11; k++) {
            const int xo = i - k;
            if (xo >= 0 && xo < 16) {
                const int j = xo % 11;
#pragma unroll
                for (int q = 0; q < 5; q++)
                    acc[q][j] = fma2(pv[q], Wp[widx(k)], acc[q][j]);
            }
        }
        if (i >= 10) {
            const int xo = i - 10;
            const int j = xo % 11;
            const u64 MU1 = acc[0][j], MU2 = acc[1][j];
            const u64 E11 = acc[2][j], E22 = acc[3][j], E12 = acc[4][j];
#pragma unroll
            for (int q = 0; q < 5; q++) acc[q][j] = 0ULL;

            const u64 M11 = mul2(MU1, MU1);
            const u64 M22 = mul2(MU2, MU2);
            const u64 M12 = mul2(MU1, MU2);
            const u64 S1  = sub2(E11, M11);
            const u64 S2  = sub2(E22, M22);
            const u64 S12 = sub2(E12, M12);
            const u64 NUM = mul2(add2(add2(M12, M12), C1p), add2(add2(S12, S12), C2p));
            const u64 DEN = mul2(add2(add2(M11, M22), C1p), add2(add2(S1, S2), C2p));
            float nl, nh, dl, dh;
            unpack2(NUM, nl, nh);
            unpack2(DEN, dl, dh);

            // low pixel: xout in [0,96) -> always inside tile and image
            lsum += __fdividef(nl, dl);
            // high pixel: guard tile width and image width
            const int xh = cbase + xo + HALF;
            if (xh < TW && (x0 + xh) < IMG_W)
                lsum += __fdividef(nh, dh);
        }
    }

    // ---------- reduction: warp shuffle -> smem -> one atomic per block ----------
#pragma unroll
    for (int off = 16; off > 0; off >>= 1)
        lsum += __shfl_xor_sync(0xffffffffu, lsum, off);
    if ((tx & 31) == 0) red[tx >> 5] = lsum;
    __syncthreads();

    if (tx == 0) {
        float bsum = red[0] + red[1] + red[2];
        atomicAdd(&g_accum, bsum);
        __threadfence();
        const unsigned int old = atomicAdd(&g_count, 1u);
        if (old == NBLOCKS - 1) {
            __threadfence();
            const float total = *(volatile float*)&g_accum;
            out[0] = 1.0f - total * (1.0f / NPIX);
            *(volatile float*)&g_accum = 0.f;
            *(volatile unsigned int*)&g_count = 0u;
        }
    }
}

extern "C" void kernel_launch(void* const* d_in, const int* in_sizes, int n_in,
                              void* d_out, int out_size) {
    const float* img1 = (const float*)d_in[0];
    const float* img2 = (const float*)d_in[1];

    const int smem = 5 * TH * WSTRIDE * (int)sizeof(u64);  // 62,080 B
    cudaFuncSetAttribute(ssim_main, cudaFuncAttributeMaxDynamicSharedMemorySize, smem);

    dim3 grid((IMG_W + TW - 1) / TW, IMG_H / TH, PLANES);  // (3, 32, 96)
    ssim_main<<<grid, NTHREADS, smem>>>(img1, img2, (float*)d_out);
}

// round 3
// speedup vs baseline: 2.2136x; 2.2136x over previous
#include <cuda_runtime.h>

#define RW 192
#define TW 182
#define TH 16
#define RH 26          // TH + 10
#define VSTRIDE 194    // even (float2-aligned); /2 = 97 odd -> conflict-free LDS.64
#define NTHREADS 192
#define IMG_W 512
#define IMG_H 512
#define PLANES 96
#define NBLOCKS (3 * 32 * 96)
#define NPIX 25165824.0f

static constexpr float W0 = 0.00102838f;
static constexpr float W1 = 0.00759876f;
static constexpr float W2 = 0.03600077f;
static constexpr float W3 = 0.10936069f;
static constexpr float W4 = 0.21300553f;
static constexpr float W5 = 0.26601172f;
static constexpr float C1V = 0.0001f;
static constexpr float C2V = 0.0009f;

__device__ float g_accum;
__device__ unsigned int g_count;

__device__ __forceinline__ float wgt(int k) {
    switch (k) {
        case 0: case 10: return W0;
        case 1: case 9:  return W1;
        case 2: case 8:  return W2;
        case 3: case 7:  return W3;
        case 4: case 6:  return W4;
        default:         return W5;
    }
}

// Vertical blur: global -> smem, transposed (scatter) accumulation.
// YSAFE=true  : every gy in [y0-5, y0+20] is in range (interior y tiles).
// YSAFE=false : per-row y guard (top/bottom tiles).
template <bool YSAFE>
__device__ __forceinline__ void vblur(const float* __restrict__ p1,
                                      const float* __restrict__ p2,
                                      float* __restrict__ v,
                                      int y0, int gx, bool xok, int tx) {
    float acc[5][11];
#pragma unroll
    for (int q = 0; q < 5; q++)
#pragma unroll
        for (int j = 0; j < 11; j++) acc[q][j] = 0.f;

#pragma unroll
    for (int r = 0; r < RH; r++) {
        const int gy = y0 - 5 + r;
        float a = 0.f, b = 0.f;
        if (YSAFE) {
            if (xok) {
                const int idx = gy * IMG_W + gx;
                a = __ldg(p1 + idx);
                b = __ldg(p2 + idx);
            }
        } else {
            const bool ok = xok && (gy >= 0) && (gy < IMG_H);
            if (ok) {
                const int idx = gy * IMG_W + gx;
                a = __ldg(p1 + idx);
                b = __ldg(p2 + idx);
            }
        }
        float pq[5];
        pq[0] = a; pq[1] = b; pq[2] = a * a; pq[3] = b * b; pq[4] = a * b;
#pragma unroll
        for (int k = 0; k < 11; k++) {
            const int o = r - k;
            if (o >= 0 && o < TH) {
                const int j = o % 11;          // compile-time after unroll
#pragma unroll
                for (int q = 0; q < 5; q++)
                    acc[q][j] = fmaf(pq[q], wgt(k), acc[q][j]);
            }
        }
        if (r >= 10) {
            const int o = r - 10;
            const int j = o % 11;
#pragma unroll
            for (int q = 0; q < 5; q++) {
                v[(q * TH + o) * VSTRIDE + tx] = acc[q][j];
                acc[q][j] = 0.f;
            }
        }
    }
}

__global__ void __launch_bounds__(NTHREADS)
ssim_main(const float* __restrict__ img1, const float* __restrict__ img2,
          float* __restrict__ out) {
    extern __shared__ float v[];          // [5][TH][VSTRIDE]
    __shared__ float red[NTHREADS / 32];

    const int tx = threadIdx.x;
    const int plane = blockIdx.z;
    const int x0 = blockIdx.x * TW;
    const int y0 = blockIdx.y * TH;

    const float* __restrict__ p1 = img1 + (size_t)plane * (IMG_W * IMG_H);
    const float* __restrict__ p2 = img2 + (size_t)plane * (IMG_W * IMG_H);

    const int gx = x0 - 5 + tx;
    const bool xok = (gx >= 0) && (gx < IMG_W);

    // ---------- Phase B: vertical blur ----------
    if (y0 >= 5 && y0 + TH + 5 <= IMG_H)
        vblur<true >(p1, p2, v, y0, gx, xok, tx);
    else
        vblur<false>(p1, p2, v, y0, gx, xok, tx);
    __syncthreads();

    // ---------- Phase C: horizontal blur + SSIM epilogue ----------
    const int row = tx & 15;      // 0..15
    const int seg = tx >> 4;      // 0..11
    const int cbase = seg * 16;
    const int xlim = (IMG_W - x0 < TW) ? (IMG_W - x0) : TW;

    float acc[5][11];
#pragma unroll
    for (int q = 0; q < 5; q++)
#pragma unroll
        for (int j = 0; j < 11; j++) acc[q][j] = 0.f;

    float lsum = 0.f;
#pragma unroll
    for (int t = 0; t < RH / 2; t++) {
        // Pair-load two consecutive raw columns (64-bit, conflict-free).
        // Pairs never straddle RW=192 since cbase+2t is even and 192 is even.
        const bool pok = (cbase + 2 * t) < RW;
        float2 pv2[5];
#pragma unroll
        for (int q = 0; q < 5; q++) {
            if (pok)
                pv2[q] = *(const float2*)(v + (q * TH + row) * VSTRIDE + cbase + 2 * t);
            else
                pv2[q] = make_float2(0.f, 0.f);
        }
#pragma unroll
        for (int half = 0; half < 2; half++) {
            const int i = 2 * t + half;
            float pv[5];
#pragma unroll
            for (int q = 0; q < 5; q++)
                pv[q] = half ? pv2[q].y : pv2[q].x;
#pragma unroll
            for (int k = 0; k < 11; k++) {
                const int xo = i - k;
                if (xo >= 0 && xo < 16) {
                    const int j = xo % 11;
#pragma unroll
                    for (int q = 0; q < 5; q++)
                        acc[q][j] = fmaf(pv[q], wgt(k), acc[q][j]);
                }
            }
            if (i >= 10) {
                const int xo = i - 10;
                const int j = xo % 11;
                const float mu1 = acc[0][j], mu2 = acc[1][j];
                const float e11 = acc[2][j], e22 = acc[3][j], e12 = acc[4][j];
#pragma unroll
                for (int q = 0; q < 5; q++) acc[q][j] = 0.f;

                const int xout = cbase + xo;
                if (xout < xlim) {
                    const float m11 = mu1 * mu1;
                    const float m22 = mu2 * mu2;
                    const float m12 = mu1 * mu2;
                    const float s1  = e11 - m11;
                    const float s2  = e22 - m22;
                    const float s12 = e12 - m12;
                    const float num = (2.f * m12 + C1V) * (2.f * s12 + C2V);
                    const float den = (m11 + m22 + C1V) * (s1 + s2 + C2V);
                    lsum += __fdividef(num, den);
                }
            }
        }
    }

    // ---------- reduction: shuffle -> smem -> one atomic per block ----------
#pragma unroll
    for (int off = 16; off > 0; off >>= 1)
        lsum += __shfl_xor_sync(0xffffffffu, lsum, off);
    if ((tx & 31) == 0) red[tx >> 5] = lsum;
    __syncthreads();

    if (tx == 0) {
        float bsum = 0.f;
#pragma unroll
        for (int w = 0; w < NTHREADS / 32; w++) bsum += red[w];
        atomicAdd(&g_accum, bsum);
        __threadfence();
        const unsigned int old = atomicAdd(&g_count, 1u);
        if (old == NBLOCKS - 1) {
            __threadfence();
            const float total = *(volatile float*)&g_accum;
            out[0] = 1.0f - total * (1.0f / NPIX);
            *(volatile float*)&g_accum = 0.f;
            *(volatile unsigned int*)&g_count = 0u;
        }
    }
}

extern "C" void kernel_launch(void* const* d_in, const int* in_sizes, int n_in,
                              void* d_out, int out_size) {
    const float* img1 = (const float*)d_in[0];
    const float* img2 = (const float*)d_in[1];

    const int smem = 5 * TH * VSTRIDE * (int)sizeof(float);  // 62,080 B
    cudaFuncSetAttribute(ssim_main, cudaFuncAttributeMaxDynamicSharedMemorySize, smem);

    dim3 grid((IMG_W + TW - 1) / TW, IMG_H / TH, PLANES);    // (3, 32, 96)
    ssim_main<<<grid, NTHREADS, smem>>>(img1, img2, (float*)d_out);
}